// round 4
// baseline (speedup 1.0000x reference)
#include <cuda_runtime.h>
#include <math.h>

// Problem constants
// B=8, N=2048, M=2048, C=512

// Scratch (allocation-free rule: __device__ globals)
__device__ float g_attn[(size_t)8 * 2048 * 2048]; // 134 MB
__device__ float g_v   [(size_t)8 * 2048 * 512];  // 33.5 MB
__device__ float g_g   [(size_t)8 * 2048 * 512];
__device__ float g_h   [(size_t)8 * 2048 * 512];

#define EPI_BIAS      0
#define EPI_BIAS_RELU 1
#define EPI_TANH_GATE 2
#define EPI_MASK      3

// Classic 128x128x8 fp32 SGEMM, 256 threads, 8x8 per thread (split 4x4 quadrants).
// TRANS_B=false: C[M,N] = A[M,K] * B[K,N]   (both row-major)
// TRANS_B=true : C[M,N] = A[M,K] * B[N,K]^T (both row-major, K-contiguous)
// Epilogues:
//   EPI_BIAS      : out = acc + aux[col]
//   EPI_BIAS_RELU : out = relu(acc + aux[col])
//   EPI_TANH_GATE : out = aux[row,col] * (1 + tanhf(acc))   (aux same shape as C)
//   EPI_MASK      : out = acc * aux[row,col]                (aux same shape as C)
template <int EPI, bool TRANS_B>
__global__ __launch_bounds__(256) void sgemm_kernel(
    const float* __restrict__ A, const float* __restrict__ Bm,
    float* __restrict__ Cm, const float* __restrict__ aux,
    int Ncols, int K,
    long sA, long sB, long sC, long sAux)
{
    const int b = blockIdx.z;
    A   += (size_t)b * sA;
    Bm  += (size_t)b * sB;
    Cm  += (size_t)b * sC;
    aux += (size_t)b * sAux;

    __shared__ float As[8][128];
    __shared__ float Bs[8][128];

    const int tid = threadIdx.x;         // 0..255
    const int tx  = tid & 15;            // 0..15
    const int ty  = tid >> 4;            // 0..15
    const int brow = blockIdx.y * 128;
    const int bcol = blockIdx.x * 128;

    // global->smem load indices
    const int aRow = tid >> 1;           // 0..127
    const int aCol = (tid & 1) * 4;      // 0 or 4
    const int bRowN = tid >> 5;          // 0..7   (NN layout)
    const int bColN = (tid & 31) * 4;    // 0..124

    float acc[8][8];
#pragma unroll
    for (int i = 0; i < 8; i++)
#pragma unroll
        for (int j = 0; j < 8; j++) acc[i][j] = 0.f;

    // prefetch first tiles into registers
    float4 a4 = *(const float4*)(A + (size_t)(brow + aRow) * K + aCol);
    float4 b4;
    if (TRANS_B) b4 = *(const float4*)(Bm + (size_t)(bcol + aRow) * K + aCol);
    else         b4 = *(const float4*)(Bm + (size_t)bRowN * Ncols + bcol + bColN);

    for (int k0 = 0; k0 < K; k0 += 8) {
        __syncthreads(); // protect previous iteration's smem reads
        As[aCol + 0][aRow] = a4.x;
        As[aCol + 1][aRow] = a4.y;
        As[aCol + 2][aRow] = a4.z;
        As[aCol + 3][aRow] = a4.w;
        if (TRANS_B) {
            Bs[aCol + 0][aRow] = b4.x;
            Bs[aCol + 1][aRow] = b4.y;
            Bs[aCol + 2][aRow] = b4.z;
            Bs[aCol + 3][aRow] = b4.w;
        } else {
            *(float4*)&Bs[bRowN][bColN] = b4;
        }
        __syncthreads();

        const int kn = k0 + 8;
        if (kn < K) { // prefetch next tile (overlaps with compute below)
            a4 = *(const float4*)(A + (size_t)(brow + aRow) * K + kn + aCol);
            if (TRANS_B) b4 = *(const float4*)(Bm + (size_t)(bcol + aRow) * K + kn + aCol);
            else         b4 = *(const float4*)(Bm + (size_t)(kn + bRowN) * Ncols + bcol + bColN);
        }

#pragma unroll
        for (int kk = 0; kk < 8; kk++) {
            float4 a0 = *(const float4*)&As[kk][ty * 4];
            float4 a1 = *(const float4*)&As[kk][64 + ty * 4];
            float4 bb0 = *(const float4*)&Bs[kk][tx * 4];
            float4 bb1 = *(const float4*)&Bs[kk][64 + tx * 4];
            float ar[8] = {a0.x, a0.y, a0.z, a0.w, a1.x, a1.y, a1.z, a1.w};
            float br[8] = {bb0.x, bb0.y, bb0.z, bb0.w, bb1.x, bb1.y, bb1.z, bb1.w};
#pragma unroll
            for (int i = 0; i < 8; i++)
#pragma unroll
                for (int j = 0; j < 8; j++)
                    acc[i][j] = fmaf(ar[i], br[j], acc[i][j]);
        }
    }

    // epilogue + store (float4 per quadrant-row)
#pragma unroll
    for (int i = 0; i < 8; i++) {
        const int r = brow + ((i < 4) ? (ty * 4 + i) : (64 + ty * 4 + (i - 4)));
#pragma unroll
        for (int q = 0; q < 2; q++) {
            const int c0 = bcol + q * 64 + tx * 4;
            float vv[4];
#pragma unroll
            for (int j = 0; j < 4; j++) {
                float v = acc[i][q * 4 + j];
                const int c = c0 + j;
                if (EPI == EPI_BIAS) {
                    v += aux[c];
                } else if (EPI == EPI_BIAS_RELU) {
                    v = fmaxf(v + aux[c], 0.f);
                } else if (EPI == EPI_TANH_GATE) {
                    const float d = aux[(size_t)r * Ncols + c];
                    v = d * (1.f + tanhf(v));
                } else { // EPI_MASK
                    v *= aux[(size_t)r * Ncols + c];
                }
                vv[j] = v;
            }
            *(float4*)(Cm + (size_t)r * Ncols + c0) =
                make_float4(vv[0], vv[1], vv[2], vv[3]);
        }
    }
}

// Nonstandard masked softmax, one 256-thread block per row of 2048.
// Denominator includes exp(0 - max) for masked (exact-zero) entries;
// positions where the score is exactly 0 emit 0.
__global__ __launch_bounds__(256) void softmax_kernel(float* __restrict__ attn)
{
    const size_t row = blockIdx.x;
    float* p = attn + row * 2048;
    const int tid = threadIdx.x;

    float vals[8];
    float mx = -1e30f;
#pragma unroll
    for (int j = 0; j < 8; j++) {
        vals[j] = p[tid + 256 * j];
        mx = fmaxf(mx, vals[j]);
    }

    __shared__ float red[256];
    red[tid] = mx;
    __syncthreads();
    for (int s = 128; s > 0; s >>= 1) {
        if (tid < s) red[tid] = fmaxf(red[tid], red[tid + s]);
        __syncthreads();
    }
    mx = red[0];
    __syncthreads();

    float ex[8];
    float sum = 0.f;
#pragma unroll
    for (int j = 0; j < 8; j++) {
        ex[j] = expf(vals[j] - mx);
        sum += ex[j];
    }
    red[tid] = sum;
    __syncthreads();
    for (int s = 128; s > 0; s >>= 1) {
        if (tid < s) red[tid] += red[tid + s];
        __syncthreads();
    }
    const float inv = 1.f / red[0];

#pragma unroll
    for (int j = 0; j < 8; j++)
        p[tid + 256 * j] = (vals[j] != 0.f) ? ex[j] * inv : 0.f;
}

extern "C" void kernel_launch(void* const* d_in, const int* in_sizes, int n_in,
                              void* d_out, int out_size)
{
    const float* dec   = (const float*)d_in[0]; // [8,2048,512]
    const float* enc   = (const float*)d_in[1]; // [8,2048,512]
    const float* trans = (const float*)d_in[2]; // [8,2048,2048]
    const float* Wv    = (const float*)d_in[3]; // [512,512]
    const float* bv    = (const float*)d_in[4]; // [512]
    const float* W1    = (const float*)d_in[5];
    const float* b1    = (const float*)d_in[6];
    const float* W2    = (const float*)d_in[7];
    const float* b2    = (const float*)d_in[8];
    float* out = (float*)d_out;                 // [8,2048,512]

    float *pv, *pattn, *pg, *ph;
    cudaGetSymbolAddress((void**)&pv,    g_v);
    cudaGetSymbolAddress((void**)&pattn, g_attn);
    cudaGetSymbolAddress((void**)&pg,    g_g);
    cudaGetSymbolAddress((void**)&ph,    g_h);

    const dim3 t(256);
    const long NC = (long)2048 * 512;   // per-batch [rows=2048, 512]
    const long NM = (long)2048 * 2048;  // per-batch [2048, 2048]

    // K1: v = enc @ Wv + bv        [16384 x 512], K=512, NN
    sgemm_kernel<EPI_BIAS, false><<<dim3(4, 128, 1), t>>>(
        enc, Wv, pv, bv, 512, 512, 0, 0, 0, 0);

    // K2: scores = dec @ enc^T, then * mask   per-batch [2048 x 2048], K=512, NT
    sgemm_kernel<EPI_MASK, true><<<dim3(16, 16, 8), t>>>(
        dec, enc, pattn, trans, 2048, 512, NC, NC, NM, NM);

    // K3: nonstandard masked softmax over last axis
    softmax_kernel<<<8 * 2048, t>>>(pattn);

    // K4: O = attn @ v; g = dec * (1 + tanh(O))   per-batch [2048 x 512], K=2048, NN
    sgemm_kernel<EPI_TANH_GATE, false><<<dim3(4, 16, 8), t>>>(
        pattn, pv, pg, dec, 512, 2048, NM, NC, NC, NC);

    // K5: h = relu(g @ W1 + b1)    [16384 x 512], K=512, NN
    sgemm_kernel<EPI_BIAS_RELU, false><<<dim3(4, 128, 1), t>>>(
        pg, W1, ph, b1, 512, 512, 0, 0, 0, 0);

    // K6: out = h @ W2 + b2        [16384 x 512], K=512, NN
    sgemm_kernel<EPI_BIAS, false><<<dim3(4, 128, 1), t>>>(
        ph, W2, out, b2, 512, 512, 0, 0, 0, 0);
}

// round 8
// speedup vs baseline: 2.0756x; 2.0756x over previous
#include <cuda_runtime.h>
#include <cuda_bf16.h>
#include <math.h>
#include <stdint.h>

// Problem constants: B=8, N=2048, M=2048, C=512
#define NB 8
#define NN 2048
#define MM 2048
#define CC 512

typedef __nv_bfloat16 bf16;

// ---------------- scratch (__device__ globals; no allocations allowed) -----
__device__ float g_attn  [(size_t)NB*NN*MM];               // fp32 scores
__device__ bf16  g_attn_h[(size_t)NB*NN*MM], g_attn_l[(size_t)NB*NN*MM];
__device__ bf16  g_dec_h [(size_t)NB*NN*CC], g_dec_l[(size_t)NB*NN*CC];
__device__ bf16  g_enc_h [(size_t)NB*MM*CC], g_enc_l[(size_t)NB*MM*CC];
__device__ bf16  g_v_h   [(size_t)NB*MM*CC], g_v_l  [(size_t)NB*MM*CC];
__device__ bf16  g_g_h   [(size_t)NB*NN*CC], g_g_l  [(size_t)NB*NN*CC];
__device__ bf16  g_h_h   [(size_t)NB*NN*CC], g_h_l  [(size_t)NB*NN*CC];
__device__ bf16  g_Wv_h  [CC*CC], g_Wv_l[CC*CC];
__device__ bf16  g_W1_h  [CC*CC], g_W1_l[CC*CC];
__device__ bf16  g_W2_h  [CC*CC], g_W2_l[CC*CC];

// ---------------- baseline-PTX helpers (sm_80-class, legal in compute_103) --
__device__ __forceinline__ uint32_t smem_u32(const void* p) {
    uint32_t a;
    asm("{ .reg .u64 t; cvta.to.shared.u64 t, %1; cvt.u32.u64 %0, t; }"
        : "=r"(a) : "l"(p));
    return a;
}

__device__ __forceinline__ void cp16(uint32_t dst, const void* src) {
    asm volatile("cp.async.cg.shared.global [%0], [%1], 16;"
                 :: "r"(dst), "l"(src) : "memory");
}
__device__ __forceinline__ void cp_commit() {
    asm volatile("cp.async.commit_group;" ::: "memory");
}
__device__ __forceinline__ void cp_wait1() {
    asm volatile("cp.async.wait_group 1;" ::: "memory");
}
__device__ __forceinline__ void cp_wait0() {
    asm volatile("cp.async.wait_group 0;" ::: "memory");
}

__device__ __forceinline__ void ldsm_x4(uint32_t* a, uint32_t addr) {
    asm volatile("ldmatrix.sync.aligned.m8n8.x4.shared.b16 {%0,%1,%2,%3}, [%4];"
                 : "=r"(a[0]), "=r"(a[1]), "=r"(a[2]), "=r"(a[3]) : "r"(addr));
}
__device__ __forceinline__ void ldsm_x2(uint32_t* b, uint32_t addr) {
    asm volatile("ldmatrix.sync.aligned.m8n8.x2.shared.b16 {%0,%1}, [%2];"
                 : "=r"(b[0]), "=r"(b[1]) : "r"(addr));
}
__device__ __forceinline__ void ldsm_x2t(uint32_t* b, uint32_t addr) {
    asm volatile("ldmatrix.sync.aligned.m8n8.x2.trans.shared.b16 {%0,%1}, [%2];"
                 : "=r"(b[0]), "=r"(b[1]) : "r"(addr));
}

__device__ __forceinline__ void mma16816(float* c, const uint32_t* a,
                                         const uint32_t* b) {
    asm volatile(
        "mma.sync.aligned.m16n8k16.row.col.f32.bf16.bf16.f32 "
        "{%0,%1,%2,%3}, {%4,%5,%6,%7}, {%8,%9}, {%0,%1,%2,%3};"
        : "+f"(c[0]), "+f"(c[1]), "+f"(c[2]), "+f"(c[3])
        : "r"(a[0]), "r"(a[1]), "r"(a[2]), "r"(a[3]), "r"(b[0]), "r"(b[1]));
}

// ---------------- smem layout constants ------------------------------------
// A tiles: [128 rows][32 k + pad -> 40 bf16] = 80B row stride, 10240B/stage.
// B NT    : same shape as A (rows = n).
// B NN    : [32 k][128 n + pad -> 136 bf16] = 272B row stride, 8704B/stage.
#define ASTG 10240u

// ---------------- split-bf16 tensor GEMM (mma.sync) -------------------------
// D[128,128] tile of A[M,K] * op(B), fp32 accum, 3-MMA split (AhBh+AhBl+AlBh).
// TRANS_B=true : B stored [n][k] K-major (NT).
// TRANS_B=false: B stored [k][n] n-major (NN), ldmatrix.trans.
// EPI: 0=bias+split(bf16 h/l out)  1=mask (fp32 out *= aux[r,c])
//      2=gate  (split out = aux[r,c]*(1+tanh(acc)))
//      3=relu(bias) split          4=bias -> fp32 out
template <int EPI, bool TRANS_B>
__global__ __launch_bounds__(256, 1) void tc_gemm(
    const bf16* __restrict__ Ah, const bf16* __restrict__ Al,
    const bf16* __restrict__ Bh, const bf16* __restrict__ Bl,
    float* __restrict__ outF, bf16* __restrict__ outH, bf16* __restrict__ outL,
    const float* __restrict__ aux,
    int K, int ldB, int ldOut, long sA, long sB, long sOut, long sAux)
{
    constexpr uint32_t BSTG = TRANS_B ? 10240u : 8704u;
    extern __shared__ char smem[];
    const uint32_t sb = smem_u32(smem);

    const int tid  = threadIdx.x;
    const int lane = tid & 31;
    const int wid  = tid >> 5;
    const int wr   = wid >> 2;   // 0..1  (warp row: 64 rows each)
    const int wc   = wid & 3;    // 0..3  (warp col: 32 cols each)
    const int bz   = blockIdx.z;

    Ah += (size_t)bz * sA;  Al += (size_t)bz * sA;
    Bh += (size_t)bz * sB;  Bl += (size_t)bz * sB;
    if (outF) outF += (size_t)bz * sOut;
    if (outH) { outH += (size_t)bz * sOut; outL += (size_t)bz * sOut; }
    aux += (size_t)bz * sAux;

    const int brow = blockIdx.y * 128;
    const int bcol = blockIdx.x * 128;

    float acc[4][4][4];
#pragma unroll
    for (int mi = 0; mi < 4; mi++)
#pragma unroll
        for (int ni = 0; ni < 4; ni++)
#pragma unroll
            for (int q = 0; q < 4; q++) acc[mi][ni][q] = 0.f;

    const uint32_t aH0 = sb;
    const uint32_t aL0 = sb + 2 * ASTG;
    const uint32_t bH0 = sb + 4 * ASTG;
    const uint32_t bL0 = bH0 + 2 * BSTG;

    const int nK = K >> 5;

    // ---- async tile loader for stage i -------------------------------------
    auto issue = [&](int i) {
        const int s  = i & 1;
        const int k0 = i << 5;
        // A hi/lo: 128 rows x 64B -> 512 x 16B chunks each
#pragma unroll
        for (int j = 0; j < 2; j++) {
            int id = tid + 256 * j;
            int r = id >> 2, cs = id & 3;
            uint32_t so = (uint32_t)(r * 80 + cs * 16);
            const bf16* g = Ah + (size_t)(brow + r) * K + k0 + cs * 8;
            cp16(aH0 + s * ASTG + so, g);
            const bf16* gl = Al + (size_t)(brow + r) * K + k0 + cs * 8;
            cp16(aL0 + s * ASTG + so, gl);
        }
        if (TRANS_B) {
#pragma unroll
            for (int j = 0; j < 2; j++) {
                int id = tid + 256 * j;
                int r = id >> 2, cs = id & 3;
                uint32_t so = (uint32_t)(r * 80 + cs * 16);
                cp16(bH0 + s * BSTG + so, Bh + (size_t)(bcol + r) * K + k0 + cs * 8);
                cp16(bL0 + s * BSTG + so, Bl + (size_t)(bcol + r) * K + k0 + cs * 8);
            }
        } else {
            // B NN: 32 k-rows x 256B -> 512 x 16B chunks each
#pragma unroll
            for (int j = 0; j < 2; j++) {
                int id = tid + 256 * j;
                int r = id >> 4, cs = id & 15;
                uint32_t so = (uint32_t)(r * 272 + cs * 16);
                cp16(bH0 + s * BSTG + so, Bh + (size_t)(k0 + r) * ldB + bcol + cs * 8);
                cp16(bL0 + s * BSTG + so, Bl + (size_t)(k0 + r) * ldB + bcol + cs * 8);
            }
        }
        cp_commit();
    };

    issue(0);

    for (int i = 0; i < nK; i++) {
        if (i + 1 < nK) { issue(i + 1); cp_wait1(); }
        else            { cp_wait0(); }
        __syncthreads();

        const int s = i & 1;
        const uint32_t aH = aH0 + s * ASTG, aL = aL0 + s * ASTG;
        const uint32_t bH = bH0 + s * BSTG, bL = bL0 + s * BSTG;

#pragma unroll
        for (int ks = 0; ks < 2; ks++) {
            const int k16 = ks * 16;
            uint32_t ah[4][4], al[4][4], bhf[4][2], blf[4][2];
#pragma unroll
            for (int mi = 0; mi < 4; mi++) {
                uint32_t off = (uint32_t)((wr * 64 + mi * 16 + (lane & 15)) * 80
                                          + k16 * 2 + (lane >> 4) * 16);
                ldsm_x4(ah[mi], aH + off);
                ldsm_x4(al[mi], aL + off);
            }
#pragma unroll
            for (int ni = 0; ni < 4; ni++) {
                if (TRANS_B) {
                    uint32_t off = (uint32_t)((wc * 32 + ni * 8 + (lane & 7)) * 80
                                              + k16 * 2 + ((lane >> 3) & 1) * 16);
                    ldsm_x2(bhf[ni], bH + off);
                    ldsm_x2(blf[ni], bL + off);
                } else {
                    uint32_t off = (uint32_t)((k16 + (lane & 15)) * 272
                                              + (wc * 32 + ni * 8) * 2);
                    ldsm_x2t(bhf[ni], bH + off);
                    ldsm_x2t(blf[ni], bL + off);
                }
            }
#pragma unroll
            for (int mi = 0; mi < 4; mi++)
#pragma unroll
                for (int ni = 0; ni < 4; ni++) {
                    mma16816(acc[mi][ni], ah[mi], bhf[ni]);
                    mma16816(acc[mi][ni], ah[mi], blf[ni]);
                    mma16816(acc[mi][ni], al[mi], bhf[ni]);
                }
        }
        __syncthreads();
    }

    // ---------------- epilogue ----------------------------------------------
    const int r_base = brow + wr * 64 + (lane >> 2);
    const int c_base = bcol + wc * 32 + (lane & 3) * 2;

#pragma unroll
    for (int mi = 0; mi < 4; mi++) {
#pragma unroll
        for (int half = 0; half < 2; half++) {
            const int r = r_base + mi * 16 + half * 8;
#pragma unroll
            for (int ni = 0; ni < 4; ni++) {
                const int c = c_base + ni * 8;
                float v0 = acc[mi][ni][half * 2 + 0];
                float v1 = acc[mi][ni][half * 2 + 1];

                if constexpr (EPI == 1) {            // scores * mask -> fp32
                    const float2 m = *(const float2*)(aux + (size_t)r * ldOut + c);
                    float2 o; o.x = v0 * m.x; o.y = v1 * m.y;
                    *(float2*)(outF + (size_t)r * ldOut + c) = o;
                } else if constexpr (EPI == 4) {     // + bias -> fp32
                    float2 o; o.x = v0 + aux[c]; o.y = v1 + aux[c + 1];
                    *(float2*)(outF + (size_t)r * ldOut + c) = o;
                } else {
                    if constexpr (EPI == 0) {        // + bias, split
                        v0 += aux[c]; v1 += aux[c + 1];
                    } else if constexpr (EPI == 3) { // relu(+bias), split
                        v0 = fmaxf(v0 + aux[c], 0.f);
                        v1 = fmaxf(v1 + aux[c + 1], 0.f);
                    } else {                         // EPI 2: gate, split
                        const float2 d = *(const float2*)(aux + (size_t)r * ldOut + c);
                        v0 = d.x * (1.f + tanhf(v0));
                        v1 = d.y * (1.f + tanhf(v1));
                    }
                    __nv_bfloat162 h2, l2;
                    h2.x = __float2bfloat16(v0);
                    h2.y = __float2bfloat16(v1);
                    l2.x = __float2bfloat16(v0 - __bfloat162float(h2.x));
                    l2.y = __float2bfloat16(v1 - __bfloat162float(h2.y));
                    *(__nv_bfloat162*)(outH + (size_t)r * ldOut + c) = h2;
                    *(__nv_bfloat162*)(outL + (size_t)r * ldOut + c) = l2;
                }
            }
        }
    }
}

// ---------------- fp32 -> bf16 hi/lo split ---------------------------------
__global__ __launch_bounds__(256) void split4_kernel(
    const float* __restrict__ x, bf16* __restrict__ h, bf16* __restrict__ l,
    int n4)
{
    int i = blockIdx.x * 256 + threadIdx.x;
    if (i >= n4) return;
    float4 v = ((const float4*)x)[i];
    float a[4] = {v.x, v.y, v.z, v.w};
    __nv_bfloat162* hp = (__nv_bfloat162*)h;
    __nv_bfloat162* lp = (__nv_bfloat162*)l;
#pragma unroll
    for (int p = 0; p < 2; p++) {
        __nv_bfloat162 h2, l2;
        h2.x = __float2bfloat16(a[p * 2 + 0]);
        h2.y = __float2bfloat16(a[p * 2 + 1]);
        l2.x = __float2bfloat16(a[p * 2 + 0] - __bfloat162float(h2.x));
        l2.y = __float2bfloat16(a[p * 2 + 1] - __bfloat162float(h2.y));
        hp[i * 2 + p] = h2;
        lp[i * 2 + p] = l2;
    }
}

// ---------------- nonstandard masked softmax + bf16 split out ---------------
__global__ __launch_bounds__(256) void softmax_kernel(
    const float* __restrict__ attn, bf16* __restrict__ oh, bf16* __restrict__ ol)
{
    const size_t row = blockIdx.x;
    const float* p = attn + row * 2048;
    const int tid = threadIdx.x;

    float vals[8];
    float mx = -1e30f;
#pragma unroll
    for (int j = 0; j < 8; j++) {
        vals[j] = p[tid + 256 * j];
        mx = fmaxf(mx, vals[j]);
    }

    __shared__ float red[256];
    red[tid] = mx;
    __syncthreads();
    for (int s = 128; s > 0; s >>= 1) {
        if (tid < s) red[tid] = fmaxf(red[tid], red[tid + s]);
        __syncthreads();
    }
    mx = red[0];
    __syncthreads();

    float ex[8], sum = 0.f;
#pragma unroll
    for (int j = 0; j < 8; j++) { ex[j] = expf(vals[j] - mx); sum += ex[j]; }
    red[tid] = sum;
    __syncthreads();
    for (int s = 128; s > 0; s >>= 1) {
        if (tid < s) red[tid] += red[tid + s];
        __syncthreads();
    }
    const float inv = 1.f / red[0];

#pragma unroll
    for (int j = 0; j < 8; j++) {
        const size_t idx = row * 2048 + tid + 256 * j;
        float w = (vals[j] != 0.f) ? ex[j] * inv : 0.f;
        bf16 h = __float2bfloat16(w);
        oh[idx] = h;
        ol[idx] = __float2bfloat16(w - __bfloat162float(h));
    }
}

// ---------------- launch ----------------------------------------------------
extern "C" void kernel_launch(void* const* d_in, const int* in_sizes, int n_in,
                              void* d_out, int out_size)
{
    const float* dec   = (const float*)d_in[0];
    const float* enc   = (const float*)d_in[1];
    const float* trans = (const float*)d_in[2];
    const float* Wv    = (const float*)d_in[3];
    const float* bv    = (const float*)d_in[4];
    const float* W1    = (const float*)d_in[5];
    const float* b1    = (const float*)d_in[6];
    const float* W2    = (const float*)d_in[7];
    const float* b2    = (const float*)d_in[8];
    float* out = (float*)d_out;

    float* pattn;
    bf16 *pattn_h, *pattn_l, *pdec_h, *pdec_l, *penc_h, *penc_l;
    bf16 *pv_h, *pv_l, *pg_h, *pg_l, *ph_h, *ph_l;
    bf16 *pWv_h, *pWv_l, *pW1_h, *pW1_l, *pW2_h, *pW2_l;
    cudaGetSymbolAddress((void**)&pattn,   g_attn);
    cudaGetSymbolAddress((void**)&pattn_h, g_attn_h);
    cudaGetSymbolAddress((void**)&pattn_l, g_attn_l);
    cudaGetSymbolAddress((void**)&pdec_h,  g_dec_h);
    cudaGetSymbolAddress((void**)&pdec_l,  g_dec_l);
    cudaGetSymbolAddress((void**)&penc_h,  g_enc_h);
    cudaGetSymbolAddress((void**)&penc_l,  g_enc_l);
    cudaGetSymbolAddress((void**)&pv_h,    g_v_h);
    cudaGetSymbolAddress((void**)&pv_l,    g_v_l);
    cudaGetSymbolAddress((void**)&pg_h,    g_g_h);
    cudaGetSymbolAddress((void**)&pg_l,    g_g_l);
    cudaGetSymbolAddress((void**)&ph_h,    g_h_h);
    cudaGetSymbolAddress((void**)&ph_l,    g_h_l);
    cudaGetSymbolAddress((void**)&pWv_h,   g_Wv_h);
    cudaGetSymbolAddress((void**)&pWv_l,   g_Wv_l);
    cudaGetSymbolAddress((void**)&pW1_h,   g_W1_h);
    cudaGetSymbolAddress((void**)&pW1_l,   g_W1_l);
    cudaGetSymbolAddress((void**)&pW2_h,   g_W2_h);
    cudaGetSymbolAddress((void**)&pW2_l,   g_W2_l);

    // dynamic smem: NT = 4*10240 + 4*10240 = 81920 ; NN = 4*10240 + 4*8704 = 75776
    const int SM_NT = 81920, SM_NN = 75776;
    cudaFuncSetAttribute(tc_gemm<0, false>, cudaFuncAttributeMaxDynamicSharedMemorySize, SM_NN);
    cudaFuncSetAttribute(tc_gemm<1, true >, cudaFuncAttributeMaxDynamicSharedMemorySize, SM_NT);
    cudaFuncSetAttribute(tc_gemm<2, false>, cudaFuncAttributeMaxDynamicSharedMemorySize, SM_NN);
    cudaFuncSetAttribute(tc_gemm<3, false>, cudaFuncAttributeMaxDynamicSharedMemorySize, SM_NN);
    cudaFuncSetAttribute(tc_gemm<4, false>, cudaFuncAttributeMaxDynamicSharedMemorySize, SM_NN);

    const long NC  = (long)NN * CC;   // 2048*512
    const long NMs = (long)NN * MM;   // 2048*2048

    // splits
    const int n4i = NB * NN * CC / 4;               // inputs
    split4_kernel<<<(n4i + 255) / 256, 256>>>(dec, pdec_h, pdec_l, n4i);
    split4_kernel<<<(n4i + 255) / 256, 256>>>(enc, penc_h, penc_l, n4i);
    const int n4w = CC * CC / 4;                    // weights
    split4_kernel<<<(n4w + 255) / 256, 256>>>(Wv, pWv_h, pWv_l, n4w);
    split4_kernel<<<(n4w + 255) / 256, 256>>>(W1, pW1_h, pW1_l, n4w);
    split4_kernel<<<(n4w + 255) / 256, 256>>>(W2, pW2_h, pW2_l, n4w);

    // K1: v = enc @ Wv + bv (NN) -> bf16 split
    tc_gemm<0, false><<<dim3(4, 128, 1), 256, SM_NN>>>(
        penc_h, penc_l, pWv_h, pWv_l, nullptr, pv_h, pv_l, bv,
        512, 512, 512, 0, 0, 0, 0);

    // K2: scores = (dec @ enc^T) * mask (NT) -> fp32
    tc_gemm<1, true><<<dim3(16, 16, 8), 256, SM_NT>>>(
        pdec_h, pdec_l, penc_h, penc_l, pattn, nullptr, nullptr, trans,
        512, 512, 2048, NC, NC, NMs, NMs);

    // K3: nonstandard masked softmax -> bf16 split attn
    softmax_kernel<<<NB * NN, 256>>>(pattn, pattn_h, pattn_l);

    // K4: g = dec * (1 + tanh(attn @ v)) (NN) -> bf16 split
    tc_gemm<2, false><<<dim3(4, 16, 8), 256, SM_NN>>>(
        pattn_h, pattn_l, pv_h, pv_l, nullptr, pg_h, pg_l, dec,
        2048, 512, 512, NMs, NC, NC, NC);

    // K5: h = relu(g @ W1 + b1) (NN) -> bf16 split
    tc_gemm<3, false><<<dim3(4, 128, 1), 256, SM_NN>>>(
        pg_h, pg_l, pW1_h, pW1_l, nullptr, ph_h, ph_l, b1,
        512, 512, 512, 0, 0, 0, 0);

    // K6: out = h @ W2 + b2 (NN) -> fp32
    tc_gemm<4, false><<<dim3(4, 128, 1), 256, SM_NN>>>(
        ph_h, ph_l, pW2_h, pW2_l, out, nullptr, nullptr, b2,
        512, 512, 512, 0, 0, 0, 0);
}

// round 10
// speedup vs baseline: 2.3081x; 1.1120x over previous
#include <cuda_runtime.h>
#include <cuda_bf16.h>
#include <math.h>
#include <stdint.h>

// Problem constants: B=8, N=2048, M=2048, C=512
#define NB 8
#define NN 2048
#define MM 2048
#define CC 512

typedef __nv_bfloat16 bf16;

// ---------------- scratch (__device__ globals; no allocations allowed) -----
__device__ float g_attn  [(size_t)NB*NN*MM];               // fp32 scores
__device__ bf16  g_attn_h[(size_t)NB*NN*MM], g_attn_l[(size_t)NB*NN*MM];
__device__ bf16  g_dec_h [(size_t)NB*NN*CC], g_dec_l[(size_t)NB*NN*CC];
__device__ bf16  g_enc_h [(size_t)NB*MM*CC], g_enc_l[(size_t)NB*MM*CC];
__device__ bf16  g_v_h   [(size_t)NB*MM*CC], g_v_l  [(size_t)NB*MM*CC];
__device__ bf16  g_g_h   [(size_t)NB*NN*CC], g_g_l  [(size_t)NB*NN*CC];
__device__ bf16  g_h_h   [(size_t)NB*NN*CC], g_h_l  [(size_t)NB*NN*CC];
__device__ bf16  g_Wv_h  [CC*CC], g_Wv_l[CC*CC];
__device__ bf16  g_W1_h  [CC*CC], g_W1_l[CC*CC];
__device__ bf16  g_W2_h  [CC*CC], g_W2_l[CC*CC];

// ---------------- baseline-PTX helpers (sm_80-class, legal in compute_103) --
__device__ __forceinline__ uint32_t smem_u32(const void* p) {
    uint32_t a;
    asm("{ .reg .u64 t; cvta.to.shared.u64 t, %1; cvt.u32.u64 %0, t; }"
        : "=r"(a) : "l"(p));
    return a;
}

__device__ __forceinline__ void cp16(uint32_t dst, const void* src) {
    asm volatile("cp.async.cg.shared.global [%0], [%1], 16;"
                 :: "r"(dst), "l"(src) : "memory");
}
__device__ __forceinline__ void cp_commit() {
    asm volatile("cp.async.commit_group;" ::: "memory");
}
__device__ __forceinline__ void cp_wait0() {
    asm volatile("cp.async.wait_group 0;" ::: "memory");
}
__device__ __forceinline__ void cp_wait1() {
    asm volatile("cp.async.wait_group 1;" ::: "memory");
}
__device__ __forceinline__ void cp_wait2() {
    asm volatile("cp.async.wait_group 2;" ::: "memory");
}

__device__ __forceinline__ void ldsm_x4(uint32_t* a, uint32_t addr) {
    asm volatile("ldmatrix.sync.aligned.m8n8.x4.shared.b16 {%0,%1,%2,%3}, [%4];"
                 : "=r"(a[0]), "=r"(a[1]), "=r"(a[2]), "=r"(a[3]) : "r"(addr));
}
__device__ __forceinline__ void ldsm_x2t(uint32_t* b, uint32_t addr) {
    asm volatile("ldmatrix.sync.aligned.m8n8.x2.trans.shared.b16 {%0,%1}, [%2];"
                 : "=r"(b[0]), "=r"(b[1]) : "r"(addr));
}

__device__ __forceinline__ void mma16816(float* c, const uint32_t* a,
                                         const uint32_t* b) {
    asm volatile(
        "mma.sync.aligned.m16n8k16.row.col.f32.bf16.bf16.f32 "
        "{%0,%1,%2,%3}, {%4,%5,%6,%7}, {%8,%9}, {%0,%1,%2,%3};"
        : "+f"(c[0]), "+f"(c[1]), "+f"(c[2]), "+f"(c[3])
        : "r"(a[0]), "r"(a[1]), "r"(a[2]), "r"(a[3]), "r"(b[0]), "r"(b[1]));
}

// ---------------- smem layout ----------------------------------------------
// A stage: 128 rows x (32k -> 80B padded row) = 10240B per matrix (hi, lo).
// B NT   : 256 rows x 80B = 20480B per matrix.
// B NN   : 32 k-rows x (256n -> 528B padded row) = 16896B per matrix.
// Stage = Ah + Al + Bh + Bl ; 3 stages.

// ---------------- split-bf16 tensor GEMM (mma.sync, 128x256 tile) ----------
// D tile [128,256] of A[M,K] * op(B), fp32 accum, 3-MMA split (AhBh+AhBl+AlBh).
// TRANS_B=true : B stored [n][k] K-major (NT).
// TRANS_B=false: B stored [k][n] n-major (NN), ldmatrix.trans.
// EPI: 0=bias+split(bf16 h/l out)  1=mask (fp32 out *= aux[r,c])
//      2=gate (split out = aux[r,c]*(1+tanh(acc)))
//      3=relu(bias) split           4=bias -> fp32 out
template <int EPI, bool TRANS_B>
__global__ __launch_bounds__(256, 1) void tc_gemm(
    const bf16* __restrict__ Ah, const bf16* __restrict__ Al,
    const bf16* __restrict__ Bh, const bf16* __restrict__ Bl,
    float* __restrict__ outF, bf16* __restrict__ outH, bf16* __restrict__ outL,
    const float* __restrict__ aux,
    int K, int ldB, int ldOut, long sA, long sB, long sOut, long sAux)
{
    constexpr uint32_t BMS = TRANS_B ? 20480u : 16896u;   // B bytes per matrix
    constexpr uint32_t STG = 20480u + 2u * BMS;           // stage bytes
    extern __shared__ char smem[];
    const uint32_t sb = smem_u32(smem);

    const int tid  = threadIdx.x;
    const int lane = tid & 31;
    const int wid  = tid >> 5;
    const int wr   = wid >> 2;   // 0..1 : 64 rows each
    const int wc   = wid & 3;    // 0..3 : 64 cols each
    const int bz   = blockIdx.z;

    Ah += (size_t)bz * sA;  Al += (size_t)bz * sA;
    Bh += (size_t)bz * sB;  Bl += (size_t)bz * sB;
    if (outF) outF += (size_t)bz * sOut;
    if (outH) { outH += (size_t)bz * sOut; outL += (size_t)bz * sOut; }
    aux += (size_t)bz * sAux;

    const int brow = blockIdx.y * 128;
    const int bcol = blockIdx.x * 256;

    float acc[4][8][4];
#pragma unroll
    for (int mi = 0; mi < 4; mi++)
#pragma unroll
        for (int ni = 0; ni < 8; ni++)
#pragma unroll
            for (int q = 0; q < 4; q++) acc[mi][ni][q] = 0.f;

    const int nK = K >> 5;

    // ---- async tile loader for stage i -------------------------------------
    auto issue = [&](int i) {
        const int s  = i % 3;
        const int k0 = i << 5;
        const uint32_t base = sb + s * STG;
        // A hi/lo: 128 rows x 64B -> 512 x 16B chunks each
#pragma unroll
        for (int j = 0; j < 2; j++) {
            int id = tid + 256 * j;
            int r = id >> 2, cs = id & 3;
            uint32_t so = (uint32_t)(r * 80 + cs * 16);
            cp16(base + so,         Ah + (size_t)(brow + r) * K + k0 + cs * 8);
            cp16(base + 10240 + so, Al + (size_t)(brow + r) * K + k0 + cs * 8);
        }
        if (TRANS_B) {
            // B NT: 256 rows x 64B -> 1024 chunks each
#pragma unroll
            for (int j = 0; j < 4; j++) {
                int id = tid + 256 * j;
                int r = id >> 2, cs = id & 3;
                uint32_t so = (uint32_t)(r * 80 + cs * 16);
                cp16(base + 20480 + so,       Bh + (size_t)(bcol + r) * K + k0 + cs * 8);
                cp16(base + 20480 + BMS + so, Bl + (size_t)(bcol + r) * K + k0 + cs * 8);
            }
        } else {
            // B NN: 32 k-rows x 512B -> 1024 chunks each
#pragma unroll
            for (int j = 0; j < 4; j++) {
                int id = tid + 256 * j;
                int r = id >> 5, cs = id & 31;
                uint32_t so = (uint32_t)(r * 528 + cs * 16);
                cp16(base + 20480 + so,       Bh + (size_t)(k0 + r) * ldB + bcol + cs * 8);
                cp16(base + 20480 + BMS + so, Bl + (size_t)(k0 + r) * ldB + bcol + cs * 8);
            }
        }
        cp_commit();
    };

    issue(0);
    issue(1);

    for (int i = 0; i < nK; i++) {
        if (i + 2 < nK) { issue(i + 2); cp_wait2(); }
        else if (i + 1 < nK) cp_wait1();
        else                 cp_wait0();
        __syncthreads();

        const uint32_t base = sb + (i % 3) * STG;
        const uint32_t aHb = base, aLb = base + 10240;
        const uint32_t bHb = base + 20480, bLb = bHb + BMS;

#pragma unroll
        for (int ks = 0; ks < 2; ks++) {
            const int k16 = ks * 16;
            uint32_t ah[4][4], al[4][4];
#pragma unroll
            for (int mi = 0; mi < 4; mi++) {
                uint32_t off = (uint32_t)((wr * 64 + mi * 16 + (lane & 15)) * 80
                                          + k16 * 2 + (lane >> 4) * 16);
                ldsm_x4(ah[mi], aHb + off);
                ldsm_x4(al[mi], aLb + off);
            }
#pragma unroll
            for (int nh = 0; nh < 2; nh++) {
                if (TRANS_B) {
                    uint32_t bh[2][4], bl[2][4];
#pragma unroll
                    for (int p = 0; p < 2; p++) {
                        int row = wc * 64 + nh * 32 + p * 16 + (lane & 7)
                                  + ((lane >> 4) & 1) * 8;
                        uint32_t off = (uint32_t)(row * 80 + k16 * 2
                                                  + ((lane >> 3) & 1) * 16);
                        ldsm_x4(bh[p], bHb + off);
                        ldsm_x4(bl[p], bLb + off);
                    }
#pragma unroll
                    for (int mi = 0; mi < 4; mi++)
#pragma unroll
                        for (int p = 0; p < 2; p++)
#pragma unroll
                            for (int q = 0; q < 2; q++) {
                                float* c = acc[mi][nh * 4 + p * 2 + q];
                                mma16816(c, ah[mi], &bh[p][q * 2]);
                                mma16816(c, ah[mi], &bl[p][q * 2]);
                                mma16816(c, al[mi], &bh[p][q * 2]);
                            }
                } else {
                    uint32_t bh[4][2], bl[4][2];
#pragma unroll
                    for (int t = 0; t < 4; t++) {
                        int ni = nh * 4 + t;
                        uint32_t off = (uint32_t)((k16 + (lane & 15)) * 528
                                                  + (wc * 64 + ni * 8) * 2);
                        ldsm_x2t(bh[t], bHb + off);
                        ldsm_x2t(bl[t], bLb + off);
                    }
#pragma unroll
                    for (int mi = 0; mi < 4; mi++)
#pragma unroll
                        for (int t = 0; t < 4; t++) {
                            float* c = acc[mi][nh * 4 + t];
                            mma16816(c, ah[mi], bh[t]);
                            mma16816(c, ah[mi], bl[t]);
                            mma16816(c, al[mi], bh[t]);
                        }
                }
            }
        }
        __syncthreads();
    }

    // ---------------- epilogue ----------------------------------------------
    const int r_base = brow + wr * 64 + (lane >> 2);
    const int c_base = bcol + wc * 64 + (lane & 3) * 2;

#pragma unroll
    for (int mi = 0; mi < 4; mi++) {
#pragma unroll
        for (int half = 0; half < 2; half++) {
            const int r = r_base + mi * 16 + half * 8;
#pragma unroll
            for (int ni = 0; ni < 8; ni++) {
                const int c = c_base + ni * 8;
                float v0 = acc[mi][ni][half * 2 + 0];
                float v1 = acc[mi][ni][half * 2 + 1];

                if constexpr (EPI == 1) {            // scores * mask -> fp32
                    const float2 m = *(const float2*)(aux + (size_t)r * ldOut + c);
                    float2 o; o.x = v0 * m.x; o.y = v1 * m.y;
                    *(float2*)(outF + (size_t)r * ldOut + c) = o;
                } else if constexpr (EPI == 4) {     // + bias -> fp32
                    float2 o; o.x = v0 + aux[c]; o.y = v1 + aux[c + 1];
                    *(float2*)(outF + (size_t)r * ldOut + c) = o;
                } else {
                    if constexpr (EPI == 0) {        // + bias, split
                        v0 += aux[c]; v1 += aux[c + 1];
                    } else if constexpr (EPI == 3) { // relu(+bias), split
                        v0 = fmaxf(v0 + aux[c], 0.f);
                        v1 = fmaxf(v1 + aux[c + 1], 0.f);
                    } else {                         // EPI 2: gate, split
                        const float2 d = *(const float2*)(aux + (size_t)r * ldOut + c);
                        v0 = d.x * (1.f + tanhf(v0));
                        v1 = d.y * (1.f + tanhf(v1));
                    }
                    __nv_bfloat162 h2, l2;
                    h2.x = __float2bfloat16(v0);
                    h2.y = __float2bfloat16(v1);
                    l2.x = __float2bfloat16(v0 - __bfloat162float(h2.x));
                    l2.y = __float2bfloat16(v1 - __bfloat162float(h2.y));
                    *(__nv_bfloat162*)(outH + (size_t)r * ldOut + c) = h2;
                    *(__nv_bfloat162*)(outL + (size_t)r * ldOut + c) = l2;
                }
            }
        }
    }
}

// ---------------- fp32 -> bf16 hi/lo split ---------------------------------
__global__ __launch_bounds__(256) void split4_kernel(
    const float* __restrict__ x, bf16* __restrict__ h, bf16* __restrict__ l,
    int n4)
{
    int i = blockIdx.x * 256 + threadIdx.x;
    if (i >= n4) return;
    float4 v = ((const float4*)x)[i];
    float a[4] = {v.x, v.y, v.z, v.w};
    __nv_bfloat162* hp = (__nv_bfloat162*)h;
    __nv_bfloat162* lp = (__nv_bfloat162*)l;
#pragma unroll
    for (int p = 0; p < 2; p++) {
        __nv_bfloat162 h2, l2;
        h2.x = __float2bfloat16(a[p * 2 + 0]);
        h2.y = __float2bfloat16(a[p * 2 + 1]);
        l2.x = __float2bfloat16(a[p * 2 + 0] - __bfloat162float(h2.x));
        l2.y = __float2bfloat16(a[p * 2 + 1] - __bfloat162float(h2.y));
        hp[i * 2 + p] = h2;
        lp[i * 2 + p] = l2;
    }
}

// ---------------- nonstandard masked softmax + bf16 split out ---------------
__global__ __launch_bounds__(256) void softmax_kernel(
    const float* __restrict__ attn, bf16* __restrict__ oh, bf16* __restrict__ ol)
{
    const size_t row = blockIdx.x;
    const float* p = attn + row * 2048;
    const int tid = threadIdx.x;

    float vals[8];
    float mx = -1e30f;
#pragma unroll
    for (int j = 0; j < 8; j++) {
        vals[j] = p[tid + 256 * j];
        mx = fmaxf(mx, vals[j]);
    }

    __shared__ float red[256];
    red[tid] = mx;
    __syncthreads();
    for (int s = 128; s > 0; s >>= 1) {
        if (tid < s) red[tid] = fmaxf(red[tid], red[tid + s]);
        __syncthreads();
    }
    mx = red[0];
    __syncthreads();

    float ex[8], sum = 0.f;
#pragma unroll
    for (int j = 0; j < 8; j++) { ex[j] = expf(vals[j] - mx); sum += ex[j]; }
    red[tid] = sum;
    __syncthreads();
    for (int s = 128; s > 0; s >>= 1) {
        if (tid < s) red[tid] += red[tid + s];
        __syncthreads();
    }
    const float inv = 1.f / red[0];

#pragma unroll
    for (int j = 0; j < 8; j++) {
        const size_t idx = row * 2048 + tid + 256 * j;
        float w = (vals[j] != 0.f) ? ex[j] * inv : 0.f;
        bf16 h = __float2bfloat16(w);
        oh[idx] = h;
        ol[idx] = __float2bfloat16(w - __bfloat162float(h));
    }
}

// ---------------- launch ----------------------------------------------------
extern "C" void kernel_launch(void* const* d_in, const int* in_sizes, int n_in,
                              void* d_out, int out_size)
{
    const float* dec   = (const float*)d_in[0];
    const float* enc   = (const float*)d_in[1];
    const float* trans = (const float*)d_in[2];
    const float* Wv    = (const float*)d_in[3];
    const float* bv    = (const float*)d_in[4];
    const float* W1    = (const float*)d_in[5];
    const float* b1    = (const float*)d_in[6];
    const float* W2    = (const float*)d_in[7];
    const float* b2    = (const float*)d_in[8];
    float* out = (float*)d_out;

    float* pattn;
    bf16 *pattn_h, *pattn_l, *pdec_h, *pdec_l, *penc_h, *penc_l;
    bf16 *pv_h, *pv_l, *pg_h, *pg_l, *ph_h, *ph_l;
    bf16 *pWv_h, *pWv_l, *pW1_h, *pW1_l, *pW2_h, *pW2_l;
    cudaGetSymbolAddress((void**)&pattn,   g_attn);
    cudaGetSymbolAddress((void**)&pattn_h, g_attn_h);
    cudaGetSymbolAddress((void**)&pattn_l, g_attn_l);
    cudaGetSymbolAddress((void**)&pdec_h,  g_dec_h);
    cudaGetSymbolAddress((void**)&pdec_l,  g_dec_l);
    cudaGetSymbolAddress((void**)&penc_h,  g_enc_h);
    cudaGetSymbolAddress((void**)&penc_l,  g_enc_l);
    cudaGetSymbolAddress((void**)&pv_h,    g_v_h);
    cudaGetSymbolAddress((void**)&pv_l,    g_v_l);
    cudaGetSymbolAddress((void**)&pg_h,    g_g_h);
    cudaGetSymbolAddress((void**)&pg_l,    g_g_l);
    cudaGetSymbolAddress((void**)&ph_h,    g_h_h);
    cudaGetSymbolAddress((void**)&ph_l,    g_h_l);
    cudaGetSymbolAddress((void**)&pWv_h,   g_Wv_h);
    cudaGetSymbolAddress((void**)&pWv_l,   g_Wv_l);
    cudaGetSymbolAddress((void**)&pW1_h,   g_W1_h);
    cudaGetSymbolAddress((void**)&pW1_l,   g_W1_l);
    cudaGetSymbolAddress((void**)&pW2_h,   g_W2_h);
    cudaGetSymbolAddress((void**)&pW2_l,   g_W2_l);

    // dynamic smem: 3 stages. NT stage=61440 -> 184320 ; NN stage=54272 -> 162816
    const int SM_NT = 184320, SM_NN = 162816;
    cudaFuncSetAttribute(tc_gemm<0, false>, cudaFuncAttributeMaxDynamicSharedMemorySize, SM_NN);
    cudaFuncSetAttribute(tc_gemm<1, true >, cudaFuncAttributeMaxDynamicSharedMemorySize, SM_NT);
    cudaFuncSetAttribute(tc_gemm<2, false>, cudaFuncAttributeMaxDynamicSharedMemorySize, SM_NN);
    cudaFuncSetAttribute(tc_gemm<3, false>, cudaFuncAttributeMaxDynamicSharedMemorySize, SM_NN);
    cudaFuncSetAttribute(tc_gemm<4, false>, cudaFuncAttributeMaxDynamicSharedMemorySize, SM_NN);

    const long NC  = (long)NN * CC;   // 2048*512
    const long NMs = (long)NN * MM;   // 2048*2048

    // splits
    const int n4i = NB * NN * CC / 4;
    split4_kernel<<<(n4i + 255) / 256, 256>>>(dec, pdec_h, pdec_l, n4i);
    split4_kernel<<<(n4i + 255) / 256, 256>>>(enc, penc_h, penc_l, n4i);
    const int n4w = CC * CC / 4;
    split4_kernel<<<(n4w + 255) / 256, 256>>>(Wv, pWv_h, pWv_l, n4w);
    split4_kernel<<<(n4w + 255) / 256, 256>>>(W1, pW1_h, pW1_l, n4w);
    split4_kernel<<<(n4w + 255) / 256, 256>>>(W2, pW2_h, pW2_l, n4w);

    // K1: v = enc @ Wv + bv (NN) -> bf16 split
    tc_gemm<0, false><<<dim3(2, 128, 1), 256, SM_NN>>>(
        penc_h, penc_l, pWv_h, pWv_l, nullptr, pv_h, pv_l, bv,
        512, 512, 512, 0, 0, 0, 0);

    // K2: scores = (dec @ enc^T) * mask (NT) -> fp32
    tc_gemm<1, true><<<dim3(8, 16, 8), 256, SM_NT>>>(
        pdec_h, pdec_l, penc_h, penc_l, pattn, nullptr, nullptr, trans,
        512, 512, 2048, NC, NC, NMs, NMs);

    // K3: nonstandard masked softmax -> bf16 split attn
    softmax_kernel<<<NB * NN, 256>>>(pattn, pattn_h, pattn_l);

    // K4: g = dec * (1 + tanh(attn @ v)) (NN) -> bf16 split
    tc_gemm<2, false><<<dim3(2, 16, 8), 256, SM_NN>>>(
        pattn_h, pattn_l, pv_h, pv_l, nullptr, pg_h, pg_l, dec,
        2048, 512, 512, NMs, NC, NC, NC);

    // K5: h = relu(g @ W1 + b1) (NN) -> bf16 split
    tc_gemm<3, false><<<dim3(2, 128, 1), 256, SM_NN>>>(
        pg_h, pg_l, pW1_h, pW1_l, nullptr, ph_h, ph_l, b1,
        512, 512, 512, 0, 0, 0, 0);

    // K6: out = h @ W2 + b2 (NN) -> fp32
    tc_gemm<4, false><<<dim3(2, 128, 1), 256, SM_NN>>>(
        ph_h, ph_l, pW2_h, pW2_l, out, nullptr, nullptr, b2,
        512, 512, 512, 0, 0, 0, 0);
}

// round 12
// speedup vs baseline: 2.7645x; 1.1977x over previous
#include <cuda_runtime.h>
#include <cuda_bf16.h>
#include <math.h>
#include <stdint.h>

// Problem constants: B=8, N=2048, M=2048, C=512
#define NB 8
#define NN 2048
#define MM 2048
#define CC 512

typedef __nv_bfloat16 bf16;

// ---------------- scratch (__device__ globals; no allocations allowed) -----
__device__ float g_attn  [(size_t)NB*NN*MM];               // fp32 raw scores
__device__ bf16  g_attn_h[(size_t)NB*NN*MM];
__device__ bf16  g_dec_h [(size_t)NB*NN*CC], g_dec_l[(size_t)NB*NN*CC];
__device__ bf16  g_enc_h [(size_t)NB*MM*CC], g_enc_l[(size_t)NB*MM*CC];
__device__ bf16  g_v_h   [(size_t)NB*MM*CC], g_v_l  [(size_t)NB*MM*CC];
__device__ bf16  g_g_h   [(size_t)NB*NN*CC], g_g_l  [(size_t)NB*NN*CC];
__device__ bf16  g_h_h   [(size_t)NB*NN*CC], g_h_l  [(size_t)NB*NN*CC];
__device__ bf16  g_Wv_h  [CC*CC], g_Wv_l[CC*CC];
__device__ bf16  g_W1_h  [CC*CC], g_W1_l[CC*CC];
__device__ bf16  g_W2_h  [CC*CC], g_W2_l[CC*CC];

// ---------------- baseline-PTX helpers (sm_80-class, legal in compute_103) --
__device__ __forceinline__ uint32_t smem_u32(const void* p) {
    uint32_t a;
    asm("{ .reg .u64 t; cvta.to.shared.u64 t, %1; cvt.u32.u64 %0, t; }"
        : "=r"(a) : "l"(p));
    return a;
}

__device__ __forceinline__ void cp16(uint32_t dst, const void* src) {
    asm volatile("cp.async.cg.shared.global [%0], [%1], 16;"
                 :: "r"(dst), "l"(src) : "memory");
}
__device__ __forceinline__ void cp_commit() {
    asm volatile("cp.async.commit_group;" ::: "memory");
}
__device__ __forceinline__ void cp_wait0() {
    asm volatile("cp.async.wait_group 0;" ::: "memory");
}
__device__ __forceinline__ void cp_wait1() {
    asm volatile("cp.async.wait_group 1;" ::: "memory");
}

__device__ __forceinline__ void ldsm_x4(uint32_t* a, uint32_t addr) {
    asm volatile("ldmatrix.sync.aligned.m8n8.x4.shared.b16 {%0,%1,%2,%3}, [%4];"
                 : "=r"(a[0]), "=r"(a[1]), "=r"(a[2]), "=r"(a[3]) : "r"(addr));
}
__device__ __forceinline__ void ldsm_x2t(uint32_t* b, uint32_t addr) {
    asm volatile("ldmatrix.sync.aligned.m8n8.x2.trans.shared.b16 {%0,%1}, [%2];"
                 : "=r"(b[0]), "=r"(b[1]) : "r"(addr));
}

__device__ __forceinline__ void mma16816(float* c, const uint32_t* a,
                                         const uint32_t* b) {
    asm volatile(
        "mma.sync.aligned.m16n8k16.row.col.f32.bf16.bf16.f32 "
        "{%0,%1,%2,%3}, {%4,%5,%6,%7}, {%8,%9}, {%0,%1,%2,%3};"
        : "+f"(c[0]), "+f"(c[1]), "+f"(c[2]), "+f"(c[3])
        : "r"(a[0]), "r"(a[1]), "r"(a[2]), "r"(a[3]), "r"(b[0]), "r"(b[1]));
}

// ---------------- smem layout (k-tile = 64) --------------------------------
// A     : 128 rows x (64k*2B=128 +16 pad -> 144B)         = 18432B / matrix
// B NT  : 256 rows x 144B                                  = 36864B / matrix
// B NN  : 64 k-rows x (256n*2B=512 +16 pad -> 528B)        = 33792B / matrix
// Stage = A(h[,l]) + B(h,l); 2 stages.

// ---------------- split-bf16 tensor GEMM (mma.sync, 128x256 tile) ----------
// D tile [128,256] of A[M,K] * op(B), fp32 accum.
// SPLIT_A=true : 3 MMAs (AhBh + AhBl + AlBh).  false: 2 MMAs (A Bh + A Bl).
// TRANS_B=true : B stored [n][k] K-major (NT).
// TRANS_B=false: B stored [k][n] n-major (NN), ldmatrix.trans.
// EPI: 0=bias+split(bf16 h/l out)  1=plain fp32 store (raw scores)
//      2=gate (split out = aux[r,c]*(1+tanh(acc)))
//      3=relu(bias) split           4=bias -> fp32 out
template <int EPI, bool TRANS_B, bool SPLIT_A>
__global__ __launch_bounds__(256, 1) void tc_gemm(
    const bf16* __restrict__ Ah, const bf16* __restrict__ Al,
    const bf16* __restrict__ Bh, const bf16* __restrict__ Bl,
    float* __restrict__ outF, bf16* __restrict__ outH, bf16* __restrict__ outL,
    const float* __restrict__ aux,
    int K, int ldB, int ldOut, long sA, long sB, long sOut, long sAux)
{
    constexpr uint32_t ASZ = 18432u;
    constexpr uint32_t BSZ = TRANS_B ? 36864u : 33792u;
    constexpr uint32_t ACNT = SPLIT_A ? 2u : 1u;
    constexpr uint32_t BOFF = ASZ * ACNT;
    constexpr uint32_t STG  = BOFF + 2u * BSZ;
    extern __shared__ char smem[];
    const uint32_t sb = smem_u32(smem);

    const int tid  = threadIdx.x;
    const int lane = tid & 31;
    const int wid  = tid >> 5;
    const int wr   = wid >> 2;   // 0..1 : 64 rows each
    const int wc   = wid & 3;    // 0..3 : 64 cols each
    const int bz   = blockIdx.z;

    Ah += (size_t)bz * sA;
    if (SPLIT_A) Al += (size_t)bz * sA;
    Bh += (size_t)bz * sB;  Bl += (size_t)bz * sB;
    if (outF) outF += (size_t)bz * sOut;
    if (outH) { outH += (size_t)bz * sOut; outL += (size_t)bz * sOut; }
    aux += (size_t)bz * sAux;

    const int brow = blockIdx.y * 128;
    const int bcol = blockIdx.x * 256;

    float acc[4][8][4];
#pragma unroll
    for (int mi = 0; mi < 4; mi++)
#pragma unroll
        for (int ni = 0; ni < 8; ni++)
#pragma unroll
            for (int q = 0; q < 4; q++) acc[mi][ni][q] = 0.f;

    const int nK = K >> 6;

    // ---- async tile loader for stage i (k-tile 64) -------------------------
    auto issue = [&](int i) {
        const int s  = i & 1;
        const int k0 = i << 6;
        const uint32_t base = sb + s * STG;
        // A: 128 rows x 128B -> 1024 x 16B chunks per matrix
#pragma unroll
        for (int j = 0; j < 4; j++) {
            int id = tid + 256 * j;
            int r = id >> 3, cs = id & 7;
            uint32_t so = (uint32_t)(r * 144 + cs * 16);
            cp16(base + so, Ah + (size_t)(brow + r) * K + k0 + cs * 8);
            if (SPLIT_A)
                cp16(base + ASZ + so, Al + (size_t)(brow + r) * K + k0 + cs * 8);
        }
        if (TRANS_B) {
            // B NT: 256 rows x 128B -> 2048 chunks per matrix
#pragma unroll
            for (int j = 0; j < 8; j++) {
                int id = tid + 256 * j;
                int r = id >> 3, cs = id & 7;
                uint32_t so = (uint32_t)(r * 144 + cs * 16);
                cp16(base + BOFF + so,       Bh + (size_t)(bcol + r) * K + k0 + cs * 8);
                cp16(base + BOFF + BSZ + so, Bl + (size_t)(bcol + r) * K + k0 + cs * 8);
            }
        } else {
            // B NN: 64 k-rows x 512B -> 2048 chunks per matrix
#pragma unroll
            for (int j = 0; j < 8; j++) {
                int id = tid + 256 * j;
                int r = id >> 5, cs = id & 31;
                uint32_t so = (uint32_t)(r * 528 + cs * 16);
                cp16(base + BOFF + so,       Bh + (size_t)(k0 + r) * ldB + bcol + cs * 8);
                cp16(base + BOFF + BSZ + so, Bl + (size_t)(k0 + r) * ldB + bcol + cs * 8);
            }
        }
        cp_commit();
    };

    issue(0);

    for (int i = 0; i < nK; i++) {
        if (i + 1 < nK) { issue(i + 1); cp_wait1(); }
        else            { cp_wait0(); }
        __syncthreads();

        const uint32_t base = sb + (i & 1) * STG;
        const uint32_t aHb = base, aLb = base + ASZ;
        const uint32_t bHb = base + BOFF, bLb = bHb + BSZ;

#pragma unroll
        for (int ks = 0; ks < 4; ks++) {
            const int kb = ks * 32;            // byte offset of this k16 chunk
            uint32_t ah[4][4], al[4][4];
#pragma unroll
            for (int mi = 0; mi < 4; mi++) {
                uint32_t off = (uint32_t)((wr * 64 + mi * 16 + (lane & 15)) * 144
                                          + kb + (lane >> 4) * 16);
                ldsm_x4(ah[mi], aHb + off);
                if (SPLIT_A) ldsm_x4(al[mi], aLb + off);
            }
#pragma unroll
            for (int nh = 0; nh < 2; nh++) {
                if (TRANS_B) {
                    uint32_t bh[2][4], bl[2][4];
#pragma unroll
                    for (int p = 0; p < 2; p++) {
                        int row = wc * 64 + nh * 32 + p * 16 + (lane & 7)
                                  + ((lane >> 4) & 1) * 8;
                        uint32_t off = (uint32_t)(row * 144 + kb
                                                  + ((lane >> 3) & 1) * 16);
                        ldsm_x4(bh[p], bHb + off);
                        ldsm_x4(bl[p], bLb + off);
                    }
#pragma unroll
                    for (int mi = 0; mi < 4; mi++)
#pragma unroll
                        for (int p = 0; p < 2; p++)
#pragma unroll
                            for (int q = 0; q < 2; q++) {
                                float* c = acc[mi][nh * 4 + p * 2 + q];
                                mma16816(c, ah[mi], &bh[p][q * 2]);
                                mma16816(c, ah[mi], &bl[p][q * 2]);
                                if (SPLIT_A) mma16816(c, al[mi], &bh[p][q * 2]);
                            }
                } else {
                    uint32_t bh[4][2], bl[4][2];
#pragma unroll
                    for (int t = 0; t < 4; t++) {
                        int ni = nh * 4 + t;
                        uint32_t off = (uint32_t)((ks * 16 + (lane & 15)) * 528
                                                  + (wc * 64 + ni * 8) * 2);
                        ldsm_x2t(bh[t], bHb + off);
                        ldsm_x2t(bl[t], bLb + off);
                    }
#pragma unroll
                    for (int mi = 0; mi < 4; mi++)
#pragma unroll
                        for (int t = 0; t < 4; t++) {
                            float* c = acc[mi][nh * 4 + t];
                            mma16816(c, ah[mi], bh[t]);
                            mma16816(c, ah[mi], bl[t]);
                            if (SPLIT_A) mma16816(c, al[mi], bh[t]);
                        }
                }
            }
        }
        __syncthreads();
    }

    // ---------------- epilogue ----------------------------------------------
    const int r_base = brow + wr * 64 + (lane >> 2);
    const int c_base = bcol + wc * 64 + (lane & 3) * 2;

#pragma unroll
    for (int mi = 0; mi < 4; mi++) {
#pragma unroll
        for (int half = 0; half < 2; half++) {
            const int r = r_base + mi * 16 + half * 8;
#pragma unroll
            for (int ni = 0; ni < 8; ni++) {
                const int c = c_base + ni * 8;
                float v0 = acc[mi][ni][half * 2 + 0];
                float v1 = acc[mi][ni][half * 2 + 1];

                if constexpr (EPI == 1) {            // raw scores -> fp32
                    float2 o; o.x = v0; o.y = v1;
                    *(float2*)(outF + (size_t)r * ldOut + c) = o;
                } else if constexpr (EPI == 4) {     // + bias -> fp32
                    float2 o; o.x = v0 + aux[c]; o.y = v1 + aux[c + 1];
                    *(float2*)(outF + (size_t)r * ldOut + c) = o;
                } else {
                    if constexpr (EPI == 0) {        // + bias, split
                        v0 += aux[c]; v1 += aux[c + 1];
                    } else if constexpr (EPI == 3) { // relu(+bias), split
                        v0 = fmaxf(v0 + aux[c], 0.f);
                        v1 = fmaxf(v1 + aux[c + 1], 0.f);
                    } else {                         // EPI 2: gate, split
                        const float2 d = *(const float2*)(aux + (size_t)r * ldOut + c);
                        v0 = d.x * (1.f + tanhf(v0));
                        v1 = d.y * (1.f + tanhf(v1));
                    }
                    __nv_bfloat162 h2, l2;
                    h2.x = __float2bfloat16(v0);
                    h2.y = __float2bfloat16(v1);
                    l2.x = __float2bfloat16(v0 - __bfloat162float(h2.x));
                    l2.y = __float2bfloat16(v1 - __bfloat162float(h2.y));
                    *(__nv_bfloat162*)(outH + (size_t)r * ldOut + c) = h2;
                    *(__nv_bfloat162*)(outL + (size_t)r * ldOut + c) = l2;
                }
            }
        }
    }
}

// ---------------- fp32 -> bf16 hi/lo split ---------------------------------
__global__ __launch_bounds__(256) void split4_kernel(
    const float* __restrict__ x, bf16* __restrict__ h, bf16* __restrict__ l,
    int n4)
{
    int i = blockIdx.x * 256 + threadIdx.x;
    if (i >= n4) return;
    float4 v = ((const float4*)x)[i];
    float a[4] = {v.x, v.y, v.z, v.w};
    __nv_bfloat162* hp = (__nv_bfloat162*)h;
    __nv_bfloat162* lp = (__nv_bfloat162*)l;
#pragma unroll
    for (int p = 0; p < 2; p++) {
        __nv_bfloat162 h2, l2;
        h2.x = __float2bfloat16(a[p * 2 + 0]);
        h2.y = __float2bfloat16(a[p * 2 + 1]);
        l2.x = __float2bfloat16(a[p * 2 + 0] - __bfloat162float(h2.x));
        l2.y = __float2bfloat16(a[p * 2 + 1] - __bfloat162float(h2.y));
        hp[i * 2 + p] = h2;
        lp[i * 2 + p] = l2;
    }
}

// ---------------- masked softmax (mask folded in) + bf16 out ----------------
// s = raw * mask ; zeros participate in softmax; re-zero where s == 0.
__global__ __launch_bounds__(256) void softmax_kernel(
    const float* __restrict__ raw, const float* __restrict__ mask,
    bf16* __restrict__ oh)
{
    const size_t row = blockIdx.x;
    const float* p = raw + row * 2048;
    const float* m = mask + row * 2048;
    const int tid = threadIdx.x;

    float vals[8];
    float mx = -1e30f;
#pragma unroll
    for (int j = 0; j < 8; j++) {
        vals[j] = p[tid + 256 * j] * m[tid + 256 * j];
        mx = fmaxf(mx, vals[j]);
    }

    __shared__ float red[256];
    red[tid] = mx;
    __syncthreads();
    for (int s = 128; s > 0; s >>= 1) {
        if (tid < s) red[tid] = fmaxf(red[tid], red[tid + s]);
        __syncthreads();
    }
    mx = red[0];
    __syncthreads();

    float ex[8], sum = 0.f;
#pragma unroll
    for (int j = 0; j < 8; j++) { ex[j] = expf(vals[j] - mx); sum += ex[j]; }
    red[tid] = sum;
    __syncthreads();
    for (int s = 128; s > 0; s >>= 1) {
        if (tid < s) red[tid] += red[tid + s];
        __syncthreads();
    }
    const float inv = 1.f / red[0];

#pragma unroll
    for (int j = 0; j < 8; j++) {
        const size_t idx = row * 2048 + tid + 256 * j;
        float w = (vals[j] != 0.f) ? ex[j] * inv : 0.f;
        oh[idx] = __float2bfloat16(w);
    }
}

// ---------------- launch ----------------------------------------------------
extern "C" void kernel_launch(void* const* d_in, const int* in_sizes, int n_in,
                              void* d_out, int out_size)
{
    const float* dec   = (const float*)d_in[0];
    const float* enc   = (const float*)d_in[1];
    const float* trans = (const float*)d_in[2];
    const float* Wv    = (const float*)d_in[3];
    const float* bv    = (const float*)d_in[4];
    const float* W1    = (const float*)d_in[5];
    const float* b1    = (const float*)d_in[6];
    const float* W2    = (const float*)d_in[7];
    const float* b2    = (const float*)d_in[8];
    float* out = (float*)d_out;

    float* pattn;
    bf16 *pattn_h, *pdec_h, *pdec_l, *penc_h, *penc_l;
    bf16 *pv_h, *pv_l, *pg_h, *pg_l, *ph_h, *ph_l;
    bf16 *pWv_h, *pWv_l, *pW1_h, *pW1_l, *pW2_h, *pW2_l;
    cudaGetSymbolAddress((void**)&pattn,   g_attn);
    cudaGetSymbolAddress((void**)&pattn_h, g_attn_h);
    cudaGetSymbolAddress((void**)&pdec_h,  g_dec_h);
    cudaGetSymbolAddress((void**)&pdec_l,  g_dec_l);
    cudaGetSymbolAddress((void**)&penc_h,  g_enc_h);
    cudaGetSymbolAddress((void**)&penc_l,  g_enc_l);
    cudaGetSymbolAddress((void**)&pv_h,    g_v_h);
    cudaGetSymbolAddress((void**)&pv_l,    g_v_l);
    cudaGetSymbolAddress((void**)&pg_h,    g_g_h);
    cudaGetSymbolAddress((void**)&pg_l,    g_g_l);
    cudaGetSymbolAddress((void**)&ph_h,    g_h_h);
    cudaGetSymbolAddress((void**)&ph_l,    g_h_l);
    cudaGetSymbolAddress((void**)&pWv_h,   g_Wv_h);
    cudaGetSymbolAddress((void**)&pWv_l,   g_Wv_l);
    cudaGetSymbolAddress((void**)&pW1_h,   g_W1_h);
    cudaGetSymbolAddress((void**)&pW1_l,   g_W1_l);
    cudaGetSymbolAddress((void**)&pW2_h,   g_W2_h);
    cudaGetSymbolAddress((void**)&pW2_l,   g_W2_l);

    // dynamic smem (2 stages, k64):
    // NT split   : 2*(2*18432 + 2*36864) = 221184
    // NN split   : 2*(2*18432 + 2*33792) = 208896
    // NN nosplitA: 2*(  18432 + 2*33792) = 172032
    const int SM_NT = 221184, SM_NN = 208896, SM_NN_NS = 172032;
    cudaFuncSetAttribute(tc_gemm<0, false, true >, cudaFuncAttributeMaxDynamicSharedMemorySize, SM_NN);
    cudaFuncSetAttribute(tc_gemm<1, true , true >, cudaFuncAttributeMaxDynamicSharedMemorySize, SM_NT);
    cudaFuncSetAttribute(tc_gemm<2, false, false>, cudaFuncAttributeMaxDynamicSharedMemorySize, SM_NN_NS);
    cudaFuncSetAttribute(tc_gemm<3, false, true >, cudaFuncAttributeMaxDynamicSharedMemorySize, SM_NN);
    cudaFuncSetAttribute(tc_gemm<4, false, true >, cudaFuncAttributeMaxDynamicSharedMemorySize, SM_NN);

    const long NC  = (long)NN * CC;   // 2048*512
    const long NMs = (long)NN * MM;   // 2048*2048

    // splits
    const int n4i = NB * NN * CC / 4;
    split4_kernel<<<(n4i + 255) / 256, 256>>>(dec, pdec_h, pdec_l, n4i);
    split4_kernel<<<(n4i + 255) / 256, 256>>>(enc, penc_h, penc_l, n4i);
    const int n4w = CC * CC / 4;
    split4_kernel<<<(n4w + 255) / 256, 256>>>(Wv, pWv_h, pWv_l, n4w);
    split4_kernel<<<(n4w + 255) / 256, 256>>>(W1, pW1_h, pW1_l, n4w);
    split4_kernel<<<(n4w + 255) / 256, 256>>>(W2, pW2_h, pW2_l, n4w);

    // K1: v = enc @ Wv + bv (NN, split) -> bf16 split
    tc_gemm<0, false, true><<<dim3(2, 128, 1), 256, SM_NN>>>(
        penc_h, penc_l, pWv_h, pWv_l, nullptr, pv_h, pv_l, bv,
        512, 512, 512, 0, 0, 0, 0);

    // K2: raw scores = dec @ enc^T (NT, split) -> fp32 (mask applied in K3)
    tc_gemm<1, true, true><<<dim3(8, 16, 8), 256, SM_NT>>>(
        pdec_h, pdec_l, penc_h, penc_l, pattn, nullptr, nullptr, trans,
        512, 512, 2048, NC, NC, NMs, NMs);

    // K3: mask + nonstandard softmax -> bf16 attn (hi only)
    softmax_kernel<<<NB * NN, 256>>>(pattn, trans, pattn_h);

    // K4: g = dec * (1 + tanh(attn @ v)) (NN, A unsplit, 2-MMA) -> bf16 split
    tc_gemm<2, false, false><<<dim3(2, 16, 8), 256, SM_NN_NS>>>(
        pattn_h, nullptr, pv_h, pv_l, nullptr, pg_h, pg_l, dec,
        2048, 512, 512, NMs, NC, NC, NC);

    // K5: h = relu(g @ W1 + b1) (NN, split) -> bf16 split
    tc_gemm<3, false, true><<<dim3(2, 128, 1), 256, SM_NN>>>(
        pg_h, pg_l, pW1_h, pW1_l, nullptr, ph_h, ph_l, b1,
        512, 512, 512, 0, 0, 0, 0);

    // K6: out = h @ W2 + b2 (NN, split) -> fp32
    tc_gemm<4, false, true><<<dim3(2, 128, 1), 256, SM_NN>>>(
        ph_h, ph_l, pW2_h, pW2_l, out, nullptr, nullptr, b2,
        512, 512, 512, 0, 0, 0, 0);
}

// round 13
// speedup vs baseline: 3.1419x; 1.1365x over previous
#include <cuda_runtime.h>
#include <cuda_bf16.h>
#include <math.h>
#include <stdint.h>

// Problem constants: B=8, N=2048, M=2048, C=512
#define NB 8
#define NN 2048
#define MM 2048
#define CC 512

typedef __nv_bfloat16 bf16;

// ---------------- scratch (__device__ globals; no allocations allowed) -----
__device__ float g_attn  [(size_t)NB*NN*MM];               // fp32 raw scores
__device__ bf16  g_attn_h[(size_t)NB*NN*MM];
__device__ bf16  g_dec_h [(size_t)NB*NN*CC], g_dec_l[(size_t)NB*NN*CC];
__device__ bf16  g_enc_h [(size_t)NB*MM*CC], g_enc_l[(size_t)NB*MM*CC];
__device__ bf16  g_v_h   [(size_t)NB*MM*CC];
__device__ bf16  g_g_h   [(size_t)NB*NN*CC], g_g_l  [(size_t)NB*NN*CC];
__device__ bf16  g_h_h   [(size_t)NB*NN*CC], g_h_l  [(size_t)NB*NN*CC];
__device__ bf16  g_Wv_h  [CC*CC], g_Wv_l[CC*CC];
__device__ bf16  g_W1_h  [CC*CC], g_W1_l[CC*CC];
__device__ bf16  g_W2_h  [CC*CC], g_W2_l[CC*CC];

// ---------------- baseline-PTX helpers (sm_80-class, legal in compute_103) --
__device__ __forceinline__ uint32_t smem_u32(const void* p) {
    uint32_t a;
    asm("{ .reg .u64 t; cvta.to.shared.u64 t, %1; cvt.u32.u64 %0, t; }"
        : "=r"(a) : "l"(p));
    return a;
}

__device__ __forceinline__ void cp16(uint32_t dst, const void* src) {
    asm volatile("cp.async.cg.shared.global [%0], [%1], 16;"
                 :: "r"(dst), "l"(src) : "memory");
}
__device__ __forceinline__ void cp_commit() {
    asm volatile("cp.async.commit_group;" ::: "memory");
}
__device__ __forceinline__ void cp_wait0() {
    asm volatile("cp.async.wait_group 0;" ::: "memory");
}
__device__ __forceinline__ void cp_wait1() {
    asm volatile("cp.async.wait_group 1;" ::: "memory");
}

__device__ __forceinline__ void ldsm_x4(uint32_t* a, uint32_t addr) {
    asm volatile("ldmatrix.sync.aligned.m8n8.x4.shared.b16 {%0,%1,%2,%3}, [%4];"
                 : "=r"(a[0]), "=r"(a[1]), "=r"(a[2]), "=r"(a[3]) : "r"(addr));
}
__device__ __forceinline__ void ldsm_x2t(uint32_t* b, uint32_t addr) {
    asm volatile("ldmatrix.sync.aligned.m8n8.x2.trans.shared.b16 {%0,%1}, [%2];"
                 : "=r"(b[0]), "=r"(b[1]) : "r"(addr));
}

__device__ __forceinline__ void mma16816(float* c, const uint32_t* a,
                                         const uint32_t* b) {
    asm volatile(
        "mma.sync.aligned.m16n8k16.row.col.f32.bf16.bf16.f32 "
        "{%0,%1,%2,%3}, {%4,%5,%6,%7}, {%8,%9}, {%0,%1,%2,%3};"
        : "+f"(c[0]), "+f"(c[1]), "+f"(c[2]), "+f"(c[3])
        : "r"(a[0]), "r"(a[1]), "r"(a[2]), "r"(a[3]), "r"(b[0]), "r"(b[1]));
}

// ---------------- smem layout (k-tile = 64) --------------------------------
// A     : 128 rows x (64k*2B=128 +16 pad -> 144B)         = 18432B / matrix
// B NT  : 256 rows x 144B                                  = 36864B / matrix
// B NN  : 64 k-rows x (256n*2B=512 +16 pad -> 528B)        = 33792B / matrix
// Stage = A(h[,l]) + B(h[,l]); 2 stages.

// ---------------- split-bf16 tensor GEMM (mma.sync, 128x256 tile) ----------
// D tile [128,256] of A[M,K] * op(B), fp32 accum.
// SPLIT_A/SPLIT_B select the number of MMAs:
//   A&B split: 3 (AhBh + AhBl + AlBh); A only: (unused); B only: 2; none: 1.
// TRANS_B=true : B stored [n][k] K-major (NT).
// TRANS_B=false: B stored [k][n] n-major (NN), ldmatrix.trans.
// EPI: 0=bias+split(bf16 h/l out)  1=plain fp32 store (raw scores)
//      2=gate (split out = aux[r,c]*(1+tanh(acc)))
//      3=relu(bias) split           4=bias -> fp32 out
//      5=bias -> bf16 hi-only out
template <int EPI, bool TRANS_B, bool SPLIT_A, bool SPLIT_B>
__global__ __launch_bounds__(256, 1) void tc_gemm(
    const bf16* __restrict__ Ah, const bf16* __restrict__ Al,
    const bf16* __restrict__ Bh, const bf16* __restrict__ Bl,
    float* __restrict__ outF, bf16* __restrict__ outH, bf16* __restrict__ outL,
    const float* __restrict__ aux,
    int K, int ldB, int ldOut, long sA, long sB, long sOut, long sAux)
{
    constexpr uint32_t ASZ = 18432u;
    constexpr uint32_t BSZ = TRANS_B ? 36864u : 33792u;
    constexpr uint32_t ACNT = SPLIT_A ? 2u : 1u;
    constexpr uint32_t BCNT = SPLIT_B ? 2u : 1u;
    constexpr uint32_t BOFF = ASZ * ACNT;
    constexpr uint32_t STG  = BOFF + BCNT * BSZ;
    extern __shared__ char smem[];
    const uint32_t sb = smem_u32(smem);

    const int tid  = threadIdx.x;
    const int lane = tid & 31;
    const int wid  = tid >> 5;
    const int wr   = wid >> 2;   // 0..1 : 64 rows each
    const int wc   = wid & 3;    // 0..3 : 64 cols each
    const int bz   = blockIdx.z;

    Ah += (size_t)bz * sA;
    if (SPLIT_A) Al += (size_t)bz * sA;
    Bh += (size_t)bz * sB;
    if (SPLIT_B) Bl += (size_t)bz * sB;
    if (outF) outF += (size_t)bz * sOut;
    if (outH) outH += (size_t)bz * sOut;
    if (outL) outL += (size_t)bz * sOut;
    aux += (size_t)bz * sAux;

    const int brow = blockIdx.y * 128;
    const int bcol = blockIdx.x * 256;

    float acc[4][8][4];
#pragma unroll
    for (int mi = 0; mi < 4; mi++)
#pragma unroll
        for (int ni = 0; ni < 8; ni++)
#pragma unroll
            for (int q = 0; q < 4; q++) acc[mi][ni][q] = 0.f;

    const int nK = K >> 6;

    // ---- async tile loader for stage i (k-tile 64) -------------------------
    auto issue = [&](int i) {
        const int s  = i & 1;
        const int k0 = i << 6;
        const uint32_t base = sb + s * STG;
        // A: 128 rows x 128B -> 1024 x 16B chunks per matrix
#pragma unroll
        for (int j = 0; j < 4; j++) {
            int id = tid + 256 * j;
            int r = id >> 3, cs = id & 7;
            uint32_t so = (uint32_t)(r * 144 + cs * 16);
            cp16(base + so, Ah + (size_t)(brow + r) * K + k0 + cs * 8);
            if (SPLIT_A)
                cp16(base + ASZ + so, Al + (size_t)(brow + r) * K + k0 + cs * 8);
        }
        if (TRANS_B) {
            // B NT: 256 rows x 128B -> 2048 chunks per matrix
#pragma unroll
            for (int j = 0; j < 8; j++) {
                int id = tid + 256 * j;
                int r = id >> 3, cs = id & 7;
                uint32_t so = (uint32_t)(r * 144 + cs * 16);
                cp16(base + BOFF + so, Bh + (size_t)(bcol + r) * K + k0 + cs * 8);
                if (SPLIT_B)
                    cp16(base + BOFF + BSZ + so,
                         Bl + (size_t)(bcol + r) * K + k0 + cs * 8);
            }
        } else {
            // B NN: 64 k-rows x 512B -> 2048 chunks per matrix
#pragma unroll
            for (int j = 0; j < 8; j++) {
                int id = tid + 256 * j;
                int r = id >> 5, cs = id & 31;
                uint32_t so = (uint32_t)(r * 528 + cs * 16);
                cp16(base + BOFF + so, Bh + (size_t)(k0 + r) * ldB + bcol + cs * 8);
                if (SPLIT_B)
                    cp16(base + BOFF + BSZ + so,
                         Bl + (size_t)(k0 + r) * ldB + bcol + cs * 8);
            }
        }
        cp_commit();
    };

    issue(0);

    for (int i = 0; i < nK; i++) {
        if (i + 1 < nK) { issue(i + 1); cp_wait1(); }
        else            { cp_wait0(); }
        __syncthreads();

        const uint32_t base = sb + (i & 1) * STG;
        const uint32_t aHb = base, aLb = base + ASZ;
        const uint32_t bHb = base + BOFF, bLb = bHb + BSZ;

#pragma unroll
        for (int ks = 0; ks < 4; ks++) {
            const int kb = ks * 32;            // byte offset of this k16 chunk
            uint32_t ah[4][4], al[4][4];
#pragma unroll
            for (int mi = 0; mi < 4; mi++) {
                uint32_t off = (uint32_t)((wr * 64 + mi * 16 + (lane & 15)) * 144
                                          + kb + (lane >> 4) * 16);
                ldsm_x4(ah[mi], aHb + off);
                if (SPLIT_A) ldsm_x4(al[mi], aLb + off);
            }
#pragma unroll
            for (int nh = 0; nh < 2; nh++) {
                if (TRANS_B) {
                    uint32_t bh[2][4], bl[2][4];
#pragma unroll
                    for (int p = 0; p < 2; p++) {
                        int row = wc * 64 + nh * 32 + p * 16 + (lane & 7)
                                  + ((lane >> 4) & 1) * 8;
                        uint32_t off = (uint32_t)(row * 144 + kb
                                                  + ((lane >> 3) & 1) * 16);
                        ldsm_x4(bh[p], bHb + off);
                        if (SPLIT_B) ldsm_x4(bl[p], bLb + off);
                    }
#pragma unroll
                    for (int mi = 0; mi < 4; mi++)
#pragma unroll
                        for (int p = 0; p < 2; p++)
#pragma unroll
                            for (int q = 0; q < 2; q++) {
                                float* c = acc[mi][nh * 4 + p * 2 + q];
                                mma16816(c, ah[mi], &bh[p][q * 2]);
                                if (SPLIT_B) mma16816(c, ah[mi], &bl[p][q * 2]);
                                if (SPLIT_A) mma16816(c, al[mi], &bh[p][q * 2]);
                            }
                } else {
                    uint32_t bh[4][2], bl[4][2];
#pragma unroll
                    for (int t = 0; t < 4; t++) {
                        int ni = nh * 4 + t;
                        uint32_t off = (uint32_t)((ks * 16 + (lane & 15)) * 528
                                                  + (wc * 64 + ni * 8) * 2);
                        ldsm_x2t(bh[t], bHb + off);
                        if (SPLIT_B) ldsm_x2t(bl[t], bLb + off);
                    }
#pragma unroll
                    for (int mi = 0; mi < 4; mi++)
#pragma unroll
                        for (int t = 0; t < 4; t++) {
                            float* c = acc[mi][nh * 4 + t];
                            mma16816(c, ah[mi], bh[t]);
                            if (SPLIT_B) mma16816(c, ah[mi], bl[t]);
                            if (SPLIT_A) mma16816(c, al[mi], bh[t]);
                        }
                }
            }
        }
        __syncthreads();
    }

    // ---------------- epilogue ----------------------------------------------
    const int r_base = brow + wr * 64 + (lane >> 2);
    const int c_base = bcol + wc * 64 + (lane & 3) * 2;

#pragma unroll
    for (int mi = 0; mi < 4; mi++) {
#pragma unroll
        for (int half = 0; half < 2; half++) {
            const int r = r_base + mi * 16 + half * 8;
#pragma unroll
            for (int ni = 0; ni < 8; ni++) {
                const int c = c_base + ni * 8;
                float v0 = acc[mi][ni][half * 2 + 0];
                float v1 = acc[mi][ni][half * 2 + 1];

                if constexpr (EPI == 1) {            // raw scores -> fp32
                    float2 o; o.x = v0; o.y = v1;
                    *(float2*)(outF + (size_t)r * ldOut + c) = o;
                } else if constexpr (EPI == 4) {     // + bias -> fp32
                    float2 o; o.x = v0 + aux[c]; o.y = v1 + aux[c + 1];
                    *(float2*)(outF + (size_t)r * ldOut + c) = o;
                } else if constexpr (EPI == 5) {     // + bias -> bf16 hi only
                    v0 += aux[c]; v1 += aux[c + 1];
                    __nv_bfloat162 h2;
                    h2.x = __float2bfloat16(v0);
                    h2.y = __float2bfloat16(v1);
                    *(__nv_bfloat162*)(outH + (size_t)r * ldOut + c) = h2;
                } else {
                    if constexpr (EPI == 0) {        // + bias, split
                        v0 += aux[c]; v1 += aux[c + 1];
                    } else if constexpr (EPI == 3) { // relu(+bias), split
                        v0 = fmaxf(v0 + aux[c], 0.f);
                        v1 = fmaxf(v1 + aux[c + 1], 0.f);
                    } else {                         // EPI 2: gate, split
                        const float2 d = *(const float2*)(aux + (size_t)r * ldOut + c);
                        v0 = d.x * (1.f + tanhf(v0));
                        v1 = d.y * (1.f + tanhf(v1));
                    }
                    __nv_bfloat162 h2, l2;
                    h2.x = __float2bfloat16(v0);
                    h2.y = __float2bfloat16(v1);
                    l2.x = __float2bfloat16(v0 - __bfloat162float(h2.x));
                    l2.y = __float2bfloat16(v1 - __bfloat162float(h2.y));
                    *(__nv_bfloat162*)(outH + (size_t)r * ldOut + c) = h2;
                    *(__nv_bfloat162*)(outL + (size_t)r * ldOut + c) = l2;
                }
            }
        }
    }
}

// ---------------- fp32 -> bf16 hi/lo split ---------------------------------
__global__ __launch_bounds__(256) void split4_kernel(
    const float* __restrict__ x, bf16* __restrict__ h, bf16* __restrict__ l,
    int n4)
{
    int i = blockIdx.x * 256 + threadIdx.x;
    if (i >= n4) return;
    float4 v = ((const float4*)x)[i];
    float a[4] = {v.x, v.y, v.z, v.w};
    __nv_bfloat162* hp = (__nv_bfloat162*)h;
    __nv_bfloat162* lp = (__nv_bfloat162*)l;
#pragma unroll
    for (int p = 0; p < 2; p++) {
        __nv_bfloat162 h2, l2;
        h2.x = __float2bfloat16(a[p * 2 + 0]);
        h2.y = __float2bfloat16(a[p * 2 + 1]);
        l2.x = __float2bfloat16(a[p * 2 + 0] - __bfloat162float(h2.x));
        l2.y = __float2bfloat16(a[p * 2 + 1] - __bfloat162float(h2.y));
        hp[i * 2 + p] = h2;
        lp[i * 2 + p] = l2;
    }
}

// ---------------- masked softmax (mask folded in) + bf16 out ----------------
// s = raw * mask ; zeros participate in softmax; re-zero where s == 0.
__global__ __launch_bounds__(256) void softmax_kernel(
    const float* __restrict__ raw, const float* __restrict__ mask,
    bf16* __restrict__ oh)
{
    const size_t row = blockIdx.x;
    const float* p = raw + row * 2048;
    const float* m = mask + row * 2048;
    const int tid = threadIdx.x;
    const int lane = tid & 31, wrp = tid >> 5;

    __shared__ float red[8];

    float vals[8];
    float mx = -1e30f;
#pragma unroll
    for (int j = 0; j < 8; j++) {
        vals[j] = p[tid + 256 * j] * m[tid + 256 * j];
        mx = fmaxf(mx, vals[j]);
    }
#pragma unroll
    for (int o = 16; o > 0; o >>= 1)
        mx = fmaxf(mx, __shfl_xor_sync(0xFFFFFFFFu, mx, o));
    if (lane == 0) red[wrp] = mx;
    __syncthreads();
    mx = red[0];
#pragma unroll
    for (int w = 1; w < 8; w++) mx = fmaxf(mx, red[w]);
    __syncthreads();

    float ex[8], sum = 0.f;
#pragma unroll
    for (int j = 0; j < 8; j++) { ex[j] = expf(vals[j] - mx); sum += ex[j]; }
#pragma unroll
    for (int o = 16; o > 0; o >>= 1)
        sum += __shfl_xor_sync(0xFFFFFFFFu, sum, o);
    if (lane == 0) red[wrp] = sum;
    __syncthreads();
    sum = red[0];
#pragma unroll
    for (int w = 1; w < 8; w++) sum += red[w];
    const float inv = 1.f / sum;

#pragma unroll
    for (int j = 0; j < 8; j++) {
        const size_t idx = row * 2048 + tid + 256 * j;
        float w = (vals[j] != 0.f) ? ex[j] * inv : 0.f;
        oh[idx] = __float2bfloat16(w);
    }
}

// ---------------- launch ----------------------------------------------------
extern "C" void kernel_launch(void* const* d_in, const int* in_sizes, int n_in,
                              void* d_out, int out_size)
{
    const float* dec   = (const float*)d_in[0];
    const float* enc   = (const float*)d_in[1];
    const float* trans = (const float*)d_in[2];
    const float* Wv    = (const float*)d_in[3];
    const float* bv    = (const float*)d_in[4];
    const float* W1    = (const float*)d_in[5];
    const float* b1    = (const float*)d_in[6];
    const float* W2    = (const float*)d_in[7];
    const float* b2    = (const float*)d_in[8];
    float* out = (float*)d_out;

    float* pattn;
    bf16 *pattn_h, *pdec_h, *pdec_l, *penc_h, *penc_l;
    bf16 *pv_h, *pg_h, *pg_l, *ph_h, *ph_l;
    bf16 *pWv_h, *pWv_l, *pW1_h, *pW1_l, *pW2_h, *pW2_l;
    cudaGetSymbolAddress((void**)&pattn,   g_attn);
    cudaGetSymbolAddress((void**)&pattn_h, g_attn_h);
    cudaGetSymbolAddress((void**)&pdec_h,  g_dec_h);
    cudaGetSymbolAddress((void**)&pdec_l,  g_dec_l);
    cudaGetSymbolAddress((void**)&penc_h,  g_enc_h);
    cudaGetSymbolAddress((void**)&penc_l,  g_enc_l);
    cudaGetSymbolAddress((void**)&pv_h,    g_v_h);
    cudaGetSymbolAddress((void**)&pg_h,    g_g_h);
    cudaGetSymbolAddress((void**)&pg_l,    g_g_l);
    cudaGetSymbolAddress((void**)&ph_h,    g_h_h);
    cudaGetSymbolAddress((void**)&ph_l,    g_h_l);
    cudaGetSymbolAddress((void**)&pWv_h,   g_Wv_h);
    cudaGetSymbolAddress((void**)&pWv_l,   g_Wv_l);
    cudaGetSymbolAddress((void**)&pW1_h,   g_W1_h);
    cudaGetSymbolAddress((void**)&pW1_l,   g_W1_l);
    cudaGetSymbolAddress((void**)&pW2_h,   g_W2_h);
    cudaGetSymbolAddress((void**)&pW2_l,   g_W2_l);

    // dynamic smem (2 stages, k64):
    // NT  split/split : 2*(2*18432 + 2*36864) = 221184
    // NN  split/split : 2*(2*18432 + 2*33792) = 208896
    // NN  uns/uns     : 2*(  18432 +   33792) = 104448
    const int SM_NT = 221184, SM_NN = 208896, SM_NN_11 = 104448;
    cudaFuncSetAttribute((const void*)tc_gemm<5, false, true , true >, cudaFuncAttributeMaxDynamicSharedMemorySize, SM_NN);
    cudaFuncSetAttribute((const void*)tc_gemm<1, true , true , true >, cudaFuncAttributeMaxDynamicSharedMemorySize, SM_NT);
    cudaFuncSetAttribute((const void*)tc_gemm<2, false, false, false>, cudaFuncAttributeMaxDynamicSharedMemorySize, SM_NN_11);
    cudaFuncSetAttribute((const void*)tc_gemm<3, false, true , true >, cudaFuncAttributeMaxDynamicSharedMemorySize, SM_NN);
    cudaFuncSetAttribute((const void*)tc_gemm<4, false, true , true >, cudaFuncAttributeMaxDynamicSharedMemorySize, SM_NN);

    const long NC  = (long)NN * CC;   // 2048*512
    const long NMs = (long)NN * MM;   // 2048*2048

    // splits
    const int n4i = NB * NN * CC / 4;
    split4_kernel<<<(n4i + 255) / 256, 256>>>(dec, pdec_h, pdec_l, n4i);
    split4_kernel<<<(n4i + 255) / 256, 256>>>(enc, penc_h, penc_l, n4i);
    const int n4w = CC * CC / 4;
    split4_kernel<<<(n4w + 255) / 256, 256>>>(Wv, pWv_h, pWv_l, n4w);
    split4_kernel<<<(n4w + 255) / 256, 256>>>(W1, pW1_h, pW1_l, n4w);
    split4_kernel<<<(n4w + 255) / 256, 256>>>(W2, pW2_h, pW2_l, n4w);

    // K1: v = enc @ Wv + bv (NN, 3-MMA split) -> bf16 hi only
    tc_gemm<5, false, true, true><<<dim3(2, 128, 1), 256, SM_NN>>>(
        penc_h, penc_l, pWv_h, pWv_l, nullptr, pv_h, nullptr, bv,
        512, 512, 512, 0, 0, 0, 0);

    // K2: raw scores = dec @ enc^T (NT, 3-MMA split) -> fp32
    tc_gemm<1, true, true, true><<<dim3(8, 16, 8), 256, SM_NT>>>(
        pdec_h, pdec_l, penc_h, penc_l, pattn, nullptr, nullptr, trans,
        512, 512, 2048, NC, NC, NMs, NMs);

    // K3: mask + nonstandard softmax -> bf16 attn (hi only)
    softmax_kernel<<<NB * NN, 256>>>(pattn, trans, pattn_h);

    // K4: g = dec * (1 + tanh(attn_h @ v_h)) (NN, 1-MMA) -> bf16 split
    tc_gemm<2, false, false, false><<<dim3(2, 16, 8), 256, SM_NN_11>>>(
        pattn_h, nullptr, pv_h, nullptr, nullptr, pg_h, pg_l, dec,
        2048, 512, 512, NMs, NC, NC, NC);

    // K5: h = relu(g @ W1 + b1) (NN, 3-MMA split) -> bf16 split
    tc_gemm<3, false, true, true><<<dim3(2, 128, 1), 256, SM_NN>>>(
        pg_h, pg_l, pW1_h, pW1_l, nullptr, ph_h, ph_l, b1,
        512, 512, 512, 0, 0, 0, 0);

    // K6: out = h @ W2 + b2 (NN, 3-MMA split) -> fp32
    tc_gemm<4, false, true, true><<<dim3(2, 128, 1), 256, SM_NN>>>(
        ph_h, ph_l, pW2_h, pW2_l, out, nullptr, nullptr, b2,
        512, 512, 512, 0, 0, 0, 0);
}